// round 7
// baseline (speedup 1.0000x reference)
#include <cuda_runtime.h>

// Problem constants (from reference)
#define S_TOK   131072
#define DIM     512
#define VOCAB   100000
#define K_SLOTS 12        // per-row token slots; P(count>12) ~ 1e-12 for this data

// Scratch (device globals — zero at module load; the pipeline restores the
// all-zero invariant every run, so graph replays are self-consistent).
__device__ int g_counts[VOCAB];              // tokens per vocab row
__device__ int g_slot[VOCAB * K_SLOTS];      // token index per (row, rank<K)
__device__ int g_novf;                       // overflow push counter (self-correcting)
__device__ int g_ovf_vidp1[S_TOK];           // overflow entries: vid+1 (0 = empty)
__device__ int g_ovf_tok[S_TOK];             // overflow entries: token index

// ---------------------------------------------------------------------------
// Kernel 1: histogram + per-row token slots.
// rank<K tokens go to the row's slot array; the (astronomically rare) rest go
// to the overflow list. No zeroing pass needed: slots are only read for
// ranks < count, overflow entries are consumed-and-cleared by their owners.
// ---------------------------------------------------------------------------
__global__ void compact_kernel(const int* __restrict__ l2_data,
                               const int* __restrict__ l2_idxs) {
    int i = blockIdx.x * blockDim.x + threadIdx.x;
    if (i >= S_TOK) return;
    if (l2_idxs[i] == 1) {
        int v = l2_data[i];
        int rank = atomicAdd(&g_counts[v], 1);
        if (rank < K_SLOTS) {
            g_slot[v * K_SLOTS + rank] = i;
        } else {
            int p = atomicAdd(&g_novf, 1);
            g_ovf_tok[p]   = i;
            g_ovf_vidp1[p] = v + 1;
        }
    }
}

// ---------------------------------------------------------------------------
// Kernel 2: row-gather update. One warp per vocab row (exact grid).
//   c==0 -> out = w                                   (single copy)
//   c>=1 -> out = 0.5*w + 0.5*(sum of token rows)/c   (single final write)
// No atomics, no seeds, no re-reads: every output byte written exactly once.
// Scratch reset is folded in race-free:
//   - counts[row] is read by its owning warp (lockstep broadcast), then lane 0
//     zeroes it — same warp, program order, no other warp touches it.
//   - overflow: each c>K row consumes exactly (c-K) entries (fixed-bound scan,
//     match-by-vid, so concurrent consumers never interfere), zeroes its own
//     entries, and atomicSub's (c-K); total subs == total pushes, so g_novf
//     returns to 0 by construction.
// ---------------------------------------------------------------------------
__global__ void update_kernel(const float4* __restrict__ x4,
                              const float4* __restrict__ w4,
                              float4* __restrict__ out4) {
    int row  = (blockIdx.x * blockDim.x + threadIdx.x) >> 5;   // warp id == row
    int lane = threadIdx.x & 31;

    int c = g_counts[row];                 // uniform across warp (broadcast)
    if (lane == 0) g_counts[row] = 0;      // reset for next replay

    long base = (long)row * (DIM / 4);

    if (c == 0) {
        // untouched row: straight copy, streaming hints (single-touch data)
        float4 a = __ldcs(&w4[base + lane]);
        float4 b = __ldcs(&w4[base + lane + 32]);
        float4 d = __ldcs(&w4[base + lane + 64]);
        float4 e = __ldcs(&w4[base + lane + 96]);
        __stcs(&out4[base + lane],      a);
        __stcs(&out4[base + lane + 32], b);
        __stcs(&out4[base + lane + 64], d);
        __stcs(&out4[base + lane + 96], e);
        return;
    }

    // --- gather + accumulate token rows ---
    float4 s0 = make_float4(0.f, 0.f, 0.f, 0.f);
    float4 s1 = s0, s2 = s0, s3 = s0;

    int nslots = (c < K_SLOTS) ? c : K_SLOTS;
    for (int t = 0; t < nslots; t++) {
        int tok = g_slot[row * K_SLOTS + t];           // warp-uniform broadcast
        const float4* src = x4 + (long)tok * (DIM / 4);
        float4 a = __ldcs(&src[lane]);
        float4 b = __ldcs(&src[lane + 32]);
        float4 d = __ldcs(&src[lane + 64]);
        float4 e = __ldcs(&src[lane + 96]);
        s0.x += a.x; s0.y += a.y; s0.z += a.z; s0.w += a.w;
        s1.x += b.x; s1.y += b.y; s1.z += b.z; s1.w += b.w;
        s2.x += d.x; s2.y += d.y; s2.z += d.z; s2.w += d.w;
        s3.x += e.x; s3.y += e.y; s3.z += e.z; s3.w += e.w;
    }

    if (c > K_SLOTS) {
        // overflow path (correct for any data; never taken for this dataset)
        int remaining = c - K_SLOTS;
        for (int b0 = 0; b0 < S_TOK && remaining > 0; b0 += 32) {
            int j  = b0 + lane;
            int vp = g_ovf_vidp1[j];
            unsigned m = __ballot_sync(0xFFFFFFFFu, vp == row + 1);
            while (m) {
                int j2 = b0 + (__ffs(m) - 1);
                m &= m - 1;
                int tok = g_ovf_tok[j2];
                const float4* src = x4 + (long)tok * (DIM / 4);
                float4 a = __ldcs(&src[lane]);
                float4 b = __ldcs(&src[lane + 32]);
                float4 d = __ldcs(&src[lane + 64]);
                float4 e = __ldcs(&src[lane + 96]);
                s0.x += a.x; s0.y += a.y; s0.z += a.z; s0.w += a.w;
                s1.x += b.x; s1.y += b.y; s1.z += b.z; s1.w += b.w;
                s2.x += d.x; s2.y += d.y; s2.z += d.z; s2.w += d.w;
                s3.x += e.x; s3.y += e.y; s3.z += e.z; s3.w += e.w;
                if (lane == 0) g_ovf_vidp1[j2] = 0;    // clear consumed entry
                remaining--;
            }
        }
        if (lane == 0) atomicSub(&g_novf, c - K_SLOTS);
    }

    // --- final EMA write ---
    float inv = 0.5f / (float)c;
    float4 w0 = __ldcs(&w4[base + lane]);
    float4 w1 = __ldcs(&w4[base + lane + 32]);
    float4 w2 = __ldcs(&w4[base + lane + 64]);
    float4 w3 = __ldcs(&w4[base + lane + 96]);
    __stcs(&out4[base + lane], make_float4(
        fmaf(s0.x, inv, 0.5f * w0.x), fmaf(s0.y, inv, 0.5f * w0.y),
        fmaf(s0.z, inv, 0.5f * w0.z), fmaf(s0.w, inv, 0.5f * w0.w)));
    __stcs(&out4[base + lane + 32], make_float4(
        fmaf(s1.x, inv, 0.5f * w1.x), fmaf(s1.y, inv, 0.5f * w1.y),
        fmaf(s1.z, inv, 0.5f * w1.z), fmaf(s1.w, inv, 0.5f * w1.w)));
    __stcs(&out4[base + lane + 64], make_float4(
        fmaf(s2.x, inv, 0.5f * w2.x), fmaf(s2.y, inv, 0.5f * w2.y),
        fmaf(s2.z, inv, 0.5f * w2.z), fmaf(s2.w, inv, 0.5f * w2.w)));
    __stcs(&out4[base + lane + 96], make_float4(
        fmaf(s3.x, inv, 0.5f * w3.x), fmaf(s3.y, inv, 0.5f * w3.y),
        fmaf(s3.z, inv, 0.5f * w3.z), fmaf(s3.w, inv, 0.5f * w3.w)));
}

// ---------------------------------------------------------------------------
extern "C" void kernel_launch(void* const* d_in, const int* in_sizes, int n_in,
                              void* d_out, int out_size) {
    const float* out_act   = (const float*)d_in[0];   // [S, D] f32
    const float* l2_weight = (const float*)d_in[1];   // [V, D] f32
    const int*   l2_data   = (const int*)d_in[2];     // [S] i32
    const int*   l2_idxs   = (const int*)d_in[3];     // [S] i32
    float* outp = (float*)d_out;                      // [V, D] f32

    (void)in_sizes; (void)n_in; (void)out_size;

    // 1. histogram + per-row token slots (scratch zero on entry)
    compact_kernel<<<S_TOK / 256, 256>>>(l2_data, l2_idxs);

    // 2. row-gather update: warp per vocab row, exact grid (100000/8 blocks)
    update_kernel<<<VOCAB / 8, 256>>>((const float4*)out_act,
                                      (const float4*)l2_weight,
                                      (float4*)outp);
}

// round 8
// speedup vs baseline: 1.3005x; 1.3005x over previous
#include <cuda_runtime.h>

// Problem constants (from reference)
#define S_TOK   131072
#define DIM     512
#define VOCAB   100000
#define K_SLOTS 15        // ranks 1..15 per row in slots; rank 0 lives in fvidp1.
                          // c<=16 needs no overflow; P(c>16), lambda=0.655: ~1e-15.

// Scratch (device globals — zero at module load; the gather kernel restores the
// all-zero invariant for everything it consumed, so graph replays are stable).
__device__ int g_counts[VOCAB];          // tokens per vocab row
__device__ int g_fvidp1[S_TOK];          // designated entry: vid+1 at token pos (0=empty)
__device__ int g_slot[VOCAB * K_SLOTS];  // token index for ranks 1..K (never needs clearing:
                                         // only ranks < count are ever read)
__device__ int g_ovf_vidp1[S_TOK];       // overflow: vid+1 at token pos (0=empty)

// ---------------------------------------------------------------------------
// Kernel 1: histogram + entry placement. The rank-0 token of each row becomes
// the row's designated entry (keyed by its own token index — no counters).
// ---------------------------------------------------------------------------
__global__ void compact_kernel(const int* __restrict__ l2_data,
                               const int* __restrict__ l2_idxs) {
    int i = blockIdx.x * blockDim.x + threadIdx.x;
    if (i >= S_TOK) return;
    if (l2_idxs[i] == 1) {
        int v = l2_data[i];
        int rank = atomicAdd(&g_counts[v], 1);
        if (rank == 0) {
            g_fvidp1[i] = v + 1;
        } else if (rank <= K_SLOTS) {
            g_slot[v * K_SLOTS + (rank - 1)] = i;
        } else {
            g_ovf_vidp1[i] = v + 1;      // astronomically rare
        }
    }
}

// ---------------------------------------------------------------------------
// Kernel 2: copy untouched rows (c==0): out = w. Warp-per-row, 4 float4/thread
// (the exact shape that measured 6.8 TB/s in R6). Reads counts, never writes
// them — untouched rows' counts are already 0, so no reset is needed here.
// MUST run before the gather kernel (which zeroes counts of touched rows).
// ---------------------------------------------------------------------------
__global__ void copy_kernel(const float4* __restrict__ w4,
                            float4* __restrict__ out4) {
    int row  = (blockIdx.x * blockDim.x + threadIdx.x) >> 5;
    int lane = threadIdx.x & 31;
    if (g_counts[row] != 0) return;       // uniform per warp

    long base = (long)row * (DIM / 4);
    float4 a = __ldcs(&w4[base + lane]);
    float4 b = __ldcs(&w4[base + lane + 32]);
    float4 d = __ldcs(&w4[base + lane + 64]);
    float4 e = __ldcs(&w4[base + lane + 96]);
    __stcs(&out4[base + lane],      a);
    __stcs(&out4[base + lane + 32], b);
    __stcs(&out4[base + lane + 64], d);
    __stcs(&out4[base + lane + 96], e);
}

// ---------------------------------------------------------------------------
// Kernel 3: gather-update touched rows. One warp per designated entry.
//   out_row = 0.5*w + (0.5/c) * sum(token rows)
// c==1 (71% of touched rows) degenerates to pure streaming: the designated
// token IS the entry index, so there are zero slot loads before the x stream.
// Single final write per output byte; no atomics, no seeds, no re-reads.
// Scratch reset folded in: the owning warp zeroes its fvidp1 entry and its
// row's count after reading them (same thread, same address, program order).
// ---------------------------------------------------------------------------
__global__ void __launch_bounds__(256, 6)
gather_kernel(const float4* __restrict__ x4,
              const float4* __restrict__ w4,
              float4* __restrict__ out4) {
    int j    = (blockIdx.x * blockDim.x + threadIdx.x) >> 5;  // entry == token idx
    int lane = threadIdx.x & 31;

    int vp1 = g_fvidp1[j];                // uniform per warp
    if (vp1 == 0) return;                 // empty entry
    int row = vp1 - 1;
    int c = g_counts[row];
    if (lane == 0) {
        g_fvidp1[j] = 0;                  // consume entry
        g_counts[row] = 0;                // reset for next replay
    }

    // accumulate: start with the designated token's row (index j)
    const float4* src0 = x4 + (long)j * (DIM / 4);
    float4 s0 = __ldcs(&src0[lane]);
    float4 s1 = __ldcs(&src0[lane + 32]);
    float4 s2 = __ldcs(&src0[lane + 64]);
    float4 s3 = __ldcs(&src0[lane + 96]);

    int nrest = c - 1;
    int ns = (nrest < K_SLOTS) ? nrest : K_SLOTS;
    for (int t = 0; t < ns; t++) {
        int tok = g_slot[row * K_SLOTS + t];          // warp-uniform broadcast
        const float4* src = x4 + (long)tok * (DIM / 4);
        float4 a = __ldcs(&src[lane]);
        float4 b = __ldcs(&src[lane + 32]);
        float4 d = __ldcs(&src[lane + 64]);
        float4 e = __ldcs(&src[lane + 96]);
        s0.x += a.x; s0.y += a.y; s0.z += a.z; s0.w += a.w;
        s1.x += b.x; s1.y += b.y; s1.z += b.z; s1.w += b.w;
        s2.x += d.x; s2.y += d.y; s2.z += d.z; s2.w += d.w;
        s3.x += e.x; s3.y += e.y; s3.z += e.z; s3.w += e.w;
    }

    if (nrest > K_SLOTS) {
        // cold overflow path: correct for any input, never taken for this data
        int remaining = nrest - K_SLOTS;
        for (int b0 = 0; b0 < S_TOK && remaining > 0; b0 += 32) {
            int vpo = g_ovf_vidp1[b0 + lane];
            unsigned m = __ballot_sync(0xFFFFFFFFu, vpo == vp1);
            while (m) {
                int j2 = b0 + (__ffs(m) - 1);
                m &= m - 1;
                const float4* src = x4 + (long)j2 * (DIM / 4);
                float4 a = src[lane];
                float4 b = src[lane + 32];
                float4 d = src[lane + 64];
                float4 e = src[lane + 96];
                s0.x += a.x; s0.y += a.y; s0.z += a.z; s0.w += a.w;
                s1.x += b.x; s1.y += b.y; s1.z += b.z; s1.w += b.w;
                s2.x += d.x; s2.y += d.y; s2.z += d.z; s2.w += d.w;
                s3.x += e.x; s3.y += e.y; s3.z += e.z; s3.w += e.w;
                if (lane == 0) g_ovf_vidp1[j2] = 0;   // consume + clear
                remaining--;
            }
        }
    }

    // final EMA write
    long base = (long)row * (DIM / 4);
    float inv = 0.5f / (float)c;
    float4 w0 = __ldcs(&w4[base + lane]);
    float4 w1 = __ldcs(&w4[base + lane + 32]);
    float4 w2 = __ldcs(&w4[base + lane + 64]);
    float4 w3 = __ldcs(&w4[base + lane + 96]);
    __stcs(&out4[base + lane], make_float4(
        fmaf(s0.x, inv, 0.5f * w0.x), fmaf(s0.y, inv, 0.5f * w0.y),
        fmaf(s0.z, inv, 0.5f * w0.z), fmaf(s0.w, inv, 0.5f * w0.w)));
    __stcs(&out4[base + lane + 32], make_float4(
        fmaf(s1.x, inv, 0.5f * w1.x), fmaf(s1.y, inv, 0.5f * w1.y),
        fmaf(s1.z, inv, 0.5f * w1.z), fmaf(s1.w, inv, 0.5f * w1.w)));
    __stcs(&out4[base + lane + 64], make_float4(
        fmaf(s2.x, inv, 0.5f * w2.x), fmaf(s2.y, inv, 0.5f * w2.y),
        fmaf(s2.z, inv, 0.5f * w2.z), fmaf(s2.w, inv, 0.5f * w2.w)));
    __stcs(&out4[base + lane + 96], make_float4(
        fmaf(s3.x, inv, 0.5f * w3.x), fmaf(s3.y, inv, 0.5f * w3.y),
        fmaf(s3.z, inv, 0.5f * w3.z), fmaf(s3.w, inv, 0.5f * w3.w)));
}

// ---------------------------------------------------------------------------
extern "C" void kernel_launch(void* const* d_in, const int* in_sizes, int n_in,
                              void* d_out, int out_size) {
    const float* out_act   = (const float*)d_in[0];   // [S, D] f32
    const float* l2_weight = (const float*)d_in[1];   // [V, D] f32
    const int*   l2_data   = (const int*)d_in[2];     // [S] i32
    const int*   l2_idxs   = (const int*)d_in[3];     // [S] i32
    float* outp = (float*)d_out;                      // [V, D] f32

    (void)in_sizes; (void)n_in; (void)out_size;

    // 1. histogram + entry placement (scratch all-zero on entry)
    compact_kernel<<<S_TOK / 256, 256>>>(l2_data, l2_idxs);

    // 2. copy untouched rows (reads counts; must precede the gather's resets)
    copy_kernel<<<VOCAB / 8, 256>>>((const float4*)l2_weight, (float4*)outp);

    // 3. gather-update touched rows + full scratch reset
    gather_kernel<<<S_TOK / 8, 256>>>((const float4*)out_act,
                                      (const float4*)l2_weight,
                                      (float4*)outp);
}

// round 9
// speedup vs baseline: 1.6677x; 1.2824x over previous
#include <cuda_runtime.h>

// Problem constants (from reference)
#define S_TOK   131072
#define DIM     512
#define VOCAB   100000
#define K_SLOTS 16        // ranks 0..15 per row; P(count>16) ~ 0 for lambda=0.655

// Scratch (device globals — zero at module load; the pipeline restores the
// all-zero invariant every run, so graph replays are self-consistent).
__device__ int g_counts[VOCAB];          // tokens per vocab row
__device__ int g_nf;                     // # designated (rank-0) tokens
__device__ int g_ftok[S_TOK];            // designated token index per touched row
__device__ int g_fvid[S_TOK];            // its vocab id
__device__ int g_slot[VOCAB * K_SLOTS];  // token index per (row, rank). Never needs
                                         // clearing: only ranks < count are read.
__device__ int g_ovf_vidp1[S_TOK];       // overflow sentinel: vid+1 at token pos (0=empty)

// ---------------------------------------------------------------------------
// Kernel 1: histogram + slot placement + designated-token list.
// ---------------------------------------------------------------------------
__global__ void compact_kernel(const int* __restrict__ l2_data,
                               const int* __restrict__ l2_idxs) {
    int i = blockIdx.x * blockDim.x + threadIdx.x;
    if (i >= S_TOK) return;
    if (l2_idxs[i] == 1) {
        int v = l2_data[i];
        int rank = atomicAdd(&g_counts[v], 1);
        if (rank < K_SLOTS) {
            g_slot[v * K_SLOTS + rank] = i;
        } else {
            g_ovf_vidp1[i] = v + 1;      // astronomically rare
        }
        if (rank == 0) {
            int pos = atomicAdd(&g_nf, 1);
            g_ftok[pos] = i;
            g_fvid[pos] = v;
        }
    }
}

// ---------------------------------------------------------------------------
// Kernel 2: c==1 rows get their final EMA here (71% of touched rows).
// One warp per designated token, grid-stride over the dense list.
// c>=2 entries just exit (finalize handles them by gather).
// ---------------------------------------------------------------------------
__global__ void store_kernel(const float4* __restrict__ x4,
                             const float4* __restrict__ w4,
                             float4* __restrict__ out4) {
    int warp0  = (blockIdx.x * blockDim.x + threadIdx.x) >> 5;
    int nwarps = (gridDim.x * blockDim.x) >> 5;
    int lane   = threadIdx.x & 31;
    int n      = g_nf;

    for (int j = warp0; j < n; j += nwarps) {
        int v = g_fvid[j];
        if (g_counts[v] != 1) continue;           // warp-uniform
        int tok = g_ftok[j];

        const float4* src = x4 + (long)tok * (DIM / 4);
        long base = (long)v * (DIM / 4);
#pragma unroll
        for (int i = 0; i < 4; i++) {
            int c = lane + i * 32;
            float4 x  = __ldcs(&src[c]);
            float4 wv = __ldcs(&w4[base + c]);
            __stcs(&out4[base + c], make_float4(
                0.5f * (wv.x + x.x), 0.5f * (wv.y + x.y),
                0.5f * (wv.z + x.z), 0.5f * (wv.w + x.w)));
        }
    }
}

// ---------------------------------------------------------------------------
// Kernel 3: finalize. Warp-per-row over ALL rows (exact grid).
//   c==0 -> out = w (streaming copy; 52% of rows — these warps saturate DRAM
//           and hide the gather warps' dependent-load latency)
//   c==1 -> skip (store pass already wrote it); reset count
//   c>=2 -> gather the c token rows from slots, single EMA write; reset count
// No atomics, no seed writes, every output byte written exactly once overall.
// Scratch reset folded in race-free (warp owns its row's count; g_nf by one
// thread; overflow sentinels cleared by their consuming row-warp).
// ---------------------------------------------------------------------------
__global__ void __launch_bounds__(256, 6)
finalize_kernel(const float4* __restrict__ x4,
                const float4* __restrict__ w4,
                float4* __restrict__ out4) {
    int row  = (blockIdx.x * blockDim.x + threadIdx.x) >> 5;
    int lane = threadIdx.x & 31;

    if (blockIdx.x == 0 && threadIdx.x == 0) g_nf = 0;   // list counter reset

    int c = g_counts[row];                 // uniform across warp
    long base = (long)row * (DIM / 4);

    if (c == 0) {
        float4 a = __ldcs(&w4[base + lane]);
        float4 b = __ldcs(&w4[base + lane + 32]);
        float4 d = __ldcs(&w4[base + lane + 64]);
        float4 e = __ldcs(&w4[base + lane + 96]);
        __stcs(&out4[base + lane],      a);
        __stcs(&out4[base + lane + 32], b);
        __stcs(&out4[base + lane + 64], d);
        __stcs(&out4[base + lane + 96], e);
        return;
    }

    if (lane == 0) g_counts[row] = 0;      // reset for next replay
    if (c == 1) return;                    // written by store pass

    // --- gather ranks 0..min(c,K)-1 ---
    float4 s0 = make_float4(0.f, 0.f, 0.f, 0.f);
    float4 s1 = s0, s2 = s0, s3 = s0;

    int ns = (c < K_SLOTS) ? c : K_SLOTS;
    for (int t = 0; t < ns; t++) {
        int tok = g_slot[row * K_SLOTS + t];          // warp-uniform broadcast
        const float4* src = x4 + (long)tok * (DIM / 4);
        float4 a = __ldcs(&src[lane]);
        float4 b = __ldcs(&src[lane + 32]);
        float4 d = __ldcs(&src[lane + 64]);
        float4 e = __ldcs(&src[lane + 96]);
        s0.x += a.x; s0.y += a.y; s0.z += a.z; s0.w += a.w;
        s1.x += b.x; s1.y += b.y; s1.z += b.z; s1.w += b.w;
        s2.x += d.x; s2.y += d.y; s2.z += d.z; s2.w += d.w;
        s3.x += e.x; s3.y += e.y; s3.z += e.z; s3.w += e.w;
    }

    if (c > K_SLOTS) {
        // cold overflow path: correct for any input, never taken for this data
        int remaining = c - K_SLOTS;
        for (int b0 = 0; b0 < S_TOK && remaining > 0; b0 += 32) {
            int vpo = g_ovf_vidp1[b0 + lane];
            unsigned m = __ballot_sync(0xFFFFFFFFu, vpo == row + 1);
            while (m) {
                int j2 = b0 + (__ffs(m) - 1);
                m &= m - 1;
                const float4* src = x4 + (long)j2 * (DIM / 4);
                float4 a = src[lane];
                float4 b = src[lane + 32];
                float4 d = src[lane + 64];
                float4 e = src[lane + 96];
                s0.x += a.x; s0.y += a.y; s0.z += a.z; s0.w += a.w;
                s1.x += b.x; s1.y += b.y; s1.z += b.z; s1.w += b.w;
                s2.x += d.x; s2.y += d.y; s2.z += d.z; s2.w += d.w;
                s3.x += e.x; s3.y += e.y; s3.z += e.z; s3.w += e.w;
                if (lane == 0) g_ovf_vidp1[j2] = 0;   // consume + clear
                remaining--;
            }
        }
    }

    // --- final EMA write ---
    float inv = 0.5f / (float)c;
    float4 w0 = __ldcs(&w4[base + lane]);
    float4 w1 = __ldcs(&w4[base + lane + 32]);
    float4 w2 = __ldcs(&w4[base + lane + 64]);
    float4 w3 = __ldcs(&w4[base + lane + 96]);
    __stcs(&out4[base + lane], make_float4(
        fmaf(s0.x, inv, 0.5f * w0.x), fmaf(s0.y, inv, 0.5f * w0.y),
        fmaf(s0.z, inv, 0.5f * w0.z), fmaf(s0.w, inv, 0.5f * w0.w)));
    __stcs(&out4[base + lane + 32], make_float4(
        fmaf(s1.x, inv, 0.5f * w1.x), fmaf(s1.y, inv, 0.5f * w1.y),
        fmaf(s1.z, inv, 0.5f * w1.z), fmaf(s1.w, inv, 0.5f * w1.w)));
    __stcs(&out4[base + lane + 64], make_float4(
        fmaf(s2.x, inv, 0.5f * w2.x), fmaf(s2.y, inv, 0.5f * w2.y),
        fmaf(s2.z, inv, 0.5f * w2.z), fmaf(s2.w, inv, 0.5f * w2.w)));
    __stcs(&out4[base + lane + 96], make_float4(
        fmaf(s3.x, inv, 0.5f * w3.x), fmaf(s3.y, inv, 0.5f * w3.y),
        fmaf(s3.z, inv, 0.5f * w3.z), fmaf(s3.w, inv, 0.5f * w3.w)));
}

// ---------------------------------------------------------------------------
extern "C" void kernel_launch(void* const* d_in, const int* in_sizes, int n_in,
                              void* d_out, int out_size) {
    const float* out_act   = (const float*)d_in[0];   // [S, D] f32
    const float* l2_weight = (const float*)d_in[1];   // [V, D] f32
    const int*   l2_data   = (const int*)d_in[2];     // [S] i32
    const int*   l2_idxs   = (const int*)d_in[3];     // [S] i32
    float* outp = (float*)d_out;                      // [V, D] f32

    (void)in_sizes; (void)n_in; (void)out_size;

    // 1. histogram + slots + designated list (scratch all-zero on entry)
    compact_kernel<<<S_TOK / 256, 256>>>(l2_data, l2_idxs);

    // 2. c==1 rows: fused final EMA, plain streaming stores
    store_kernel<<<2960, 256>>>((const float4*)out_act,
                                (const float4*)l2_weight,
                                (float4*)outp);

    // 3. finalize: c==0 copy + c>=2 gather-EMA + scratch reset (warp-per-row)
    finalize_kernel<<<VOCAB / 8, 256>>>((const float4*)out_act,
                                        (const float4*)l2_weight,
                                        (float4*)outp);
}

// round 10
// speedup vs baseline: 1.8382x; 1.1022x over previous
#include <cuda_runtime.h>

// Problem constants (from reference)
#define S_TOK   131072
#define DIM     512
#define VOCAB   100000
#define K_SLOTS 16        // ranks 0..15 per row; P(count>16) ~ 0 for lambda=0.655

// Scratch (device globals — zero at module load; the update kernel restores the
// all-zero invariant every run, so graph replays are self-consistent).
__device__ int g_counts[VOCAB];          // tokens per vocab row
__device__ int g_slot[VOCAB * K_SLOTS];  // token index per (row, rank). Never needs
                                         // clearing: only ranks < count are read.
__device__ int g_ovf_vidp1[S_TOK];       // overflow sentinel: vid+1 at token pos (0=empty)

// ---------------------------------------------------------------------------
// Kernel 1: histogram + slot placement. 4 tokens per thread via int4 loads so
// each thread carries 4 independent atomic chains (MLP=4). No hot counters —
// the only atomics are the scattered per-row counts.
// ---------------------------------------------------------------------------
__global__ void compact_kernel(const int4* __restrict__ l2_data4,
                               const int4* __restrict__ l2_idxs4) {
    int i = blockIdx.x * blockDim.x + threadIdx.x;   // i < S_TOK/4
    int4 idx = l2_idxs4[i];
    int4 dat = l2_data4[i];
    int base = i * 4;

    if (idx.x == 1) {
        int r = atomicAdd(&g_counts[dat.x], 1);
        if (r < K_SLOTS) g_slot[dat.x * K_SLOTS + r] = base;
        else             g_ovf_vidp1[base] = dat.x + 1;
    }
    if (idx.y == 1) {
        int r = atomicAdd(&g_counts[dat.y], 1);
        if (r < K_SLOTS) g_slot[dat.y * K_SLOTS + r] = base + 1;
        else             g_ovf_vidp1[base + 1] = dat.y + 1;
    }
    if (idx.z == 1) {
        int r = atomicAdd(&g_counts[dat.z], 1);
        if (r < K_SLOTS) g_slot[dat.z * K_SLOTS + r] = base + 2;
        else             g_ovf_vidp1[base + 2] = dat.z + 1;
    }
    if (idx.w == 1) {
        int r = atomicAdd(&g_counts[dat.w], 1);
        if (r < K_SLOTS) g_slot[dat.w * K_SLOTS + r] = base + 3;
        else             g_ovf_vidp1[base + 3] = dat.w + 1;
    }
}

// ---------------------------------------------------------------------------
// Kernel 2: update. Warp-per-row over ALL rows (exact grid: VOCAB/8 blocks).
//   c==0 -> out = w (streaming copy; 52% of rows — saturates DRAM and hides
//           the gather warps' dependent-load latency)
//   c>=1 -> gather the c token rows from slots, single EMA write
// No atomics, no seed writes: every output byte written exactly once, every
// input byte read exactly once. Scratch reset folded in race-free (each warp
// owns its row's count; overflow sentinels cleared by their consuming warp).
// ---------------------------------------------------------------------------
__global__ void __launch_bounds__(256, 6)
update_kernel(const float4* __restrict__ x4,
              const float4* __restrict__ w4,
              float4* __restrict__ out4) {
    int row  = (blockIdx.x * blockDim.x + threadIdx.x) >> 5;
    int lane = threadIdx.x & 31;

    int c = g_counts[row];                 // uniform across warp
    long base = (long)row * (DIM / 4);

    if (c == 0) {
        float4 a = __ldcs(&w4[base + lane]);
        float4 b = __ldcs(&w4[base + lane + 32]);
        float4 d = __ldcs(&w4[base + lane + 64]);
        float4 e = __ldcs(&w4[base + lane + 96]);
        __stcs(&out4[base + lane],      a);
        __stcs(&out4[base + lane + 32], b);
        __stcs(&out4[base + lane + 64], d);
        __stcs(&out4[base + lane + 96], e);
        return;
    }

    if (lane == 0) g_counts[row] = 0;      // reset for next replay

    // --- gather ranks 0..min(c,K)-1 ---
    float4 s0 = make_float4(0.f, 0.f, 0.f, 0.f);
    float4 s1 = s0, s2 = s0, s3 = s0;

    int ns = (c < K_SLOTS) ? c : K_SLOTS;
    for (int t = 0; t < ns; t++) {
        int tok = g_slot[row * K_SLOTS + t];          // warp-uniform broadcast
        const float4* src = x4 + (long)tok * (DIM / 4);
        float4 a = __ldcs(&src[lane]);
        float4 b = __ldcs(&src[lane + 32]);
        float4 d = __ldcs(&src[lane + 64]);
        float4 e = __ldcs(&src[lane + 96]);
        s0.x += a.x; s0.y += a.y; s0.z += a.z; s0.w += a.w;
        s1.x += b.x; s1.y += b.y; s1.z += b.z; s1.w += b.w;
        s2.x += d.x; s2.y += d.y; s2.z += d.z; s2.w += d.w;
        s3.x += e.x; s3.y += e.y; s3.z += e.z; s3.w += e.w;
    }

    if (c > K_SLOTS) {
        // cold overflow path: correct for any input, never taken for this data
        int remaining = c - K_SLOTS;
        for (int b0 = 0; b0 < S_TOK && remaining > 0; b0 += 32) {
            int vpo = g_ovf_vidp1[b0 + lane];
            unsigned m = __ballot_sync(0xFFFFFFFFu, vpo == row + 1);
            while (m) {
                int j2 = b0 + (__ffs(m) - 1);
                m &= m - 1;
                const float4* src = x4 + (long)j2 * (DIM / 4);
                float4 a = src[lane];
                float4 b = src[lane + 32];
                float4 d = src[lane + 64];
                float4 e = src[lane + 96];
                s0.x += a.x; s0.y += a.y; s0.z += a.z; s0.w += a.w;
                s1.x += b.x; s1.y += b.y; s1.z += b.z; s1.w += b.w;
                s2.x += d.x; s2.y += d.y; s2.z += d.z; s2.w += d.w;
                s3.x += e.x; s3.y += e.y; s3.z += e.z; s3.w += e.w;
                if (lane == 0) g_ovf_vidp1[j2] = 0;   // consume + clear
                remaining--;
            }
        }
    }

    // --- final EMA write ---
    float inv = 0.5f / (float)c;
    float4 w0 = __ldcs(&w4[base + lane]);
    float4 w1 = __ldcs(&w4[base + lane + 32]);
    float4 w2 = __ldcs(&w4[base + lane + 64]);
    float4 w3 = __ldcs(&w4[base + lane + 96]);
    __stcs(&out4[base + lane], make_float4(
        fmaf(s0.x, inv, 0.5f * w0.x), fmaf(s0.y, inv, 0.5f * w0.y),
        fmaf(s0.z, inv, 0.5f * w0.z), fmaf(s0.w, inv, 0.5f * w0.w)));
    __stcs(&out4[base + lane + 32], make_float4(
        fmaf(s1.x, inv, 0.5f * w1.x), fmaf(s1.y, inv, 0.5f * w1.y),
        fmaf(s1.z, inv, 0.5f * w1.z), fmaf(s1.w, inv, 0.5f * w1.w)));
    __stcs(&out4[base + lane + 64], make_float4(
        fmaf(s2.x, inv, 0.5f * w2.x), fmaf(s2.y, inv, 0.5f * w2.y),
        fmaf(s2.z, inv, 0.5f * w2.z), fmaf(s2.w, inv, 0.5f * w2.w)));
    __stcs(&out4[base + lane + 96], make_float4(
        fmaf(s3.x, inv, 0.5f * w3.x), fmaf(s3.y, inv, 0.5f * w3.y),
        fmaf(s3.z, inv, 0.5f * w3.z), fmaf(s3.w, inv, 0.5f * w3.w)));
}

// ---------------------------------------------------------------------------
extern "C" void kernel_launch(void* const* d_in, const int* in_sizes, int n_in,
                              void* d_out, int out_size) {
    const float* out_act   = (const float*)d_in[0];   // [S, D] f32
    const float* l2_weight = (const float*)d_in[1];   // [V, D] f32
    const int*   l2_data   = (const int*)d_in[2];     // [S] i32
    const int*   l2_idxs   = (const int*)d_in[3];     // [S] i32
    float* outp = (float*)d_out;                      // [V, D] f32

    (void)in_sizes; (void)n_in; (void)out_size;

    // 1. histogram + slots (scratch all-zero on entry; 4 tokens/thread)
    compact_kernel<<<S_TOK / 4 / 256, 256>>>((const int4*)l2_data,
                                             (const int4*)l2_idxs);

    // 2. update: c==0 copy + c>=1 gather-EMA + scratch reset (warp-per-row)
    update_kernel<<<VOCAB / 8, 256>>>((const float4*)out_act,
                                      (const float4*)l2_weight,
                                      (float4*)outp);
}